// round 10
// baseline (speedup 1.0000x reference)
#include <cuda_runtime.h>
#include <cuda_bf16.h>
#include <mma.h>
#include <cstdint>

using namespace nvcuda;

#define BATCH 4
#define T_SEQ 1024
#define CDIM  512
#define NH    8
#define HDIM  64
#define SCALE_F 0.125f

// ---------------------------------------------------------------------------
// Scratch (no cudaMalloc allowed). Referenced ONLY from device code.
// ---------------------------------------------------------------------------
__device__ __align__(16) float g_q[BATCH * NH * T_SEQ * HDIM];
__device__ __align__(16) float g_k[BATCH * NH * T_SEQ * HDIM];
__device__ __align__(16) float g_v[BATCH * NH * T_SEQ * HDIM];
__device__ __align__(16) float g_y[BATCH * T_SEQ * CDIM];

__device__ __align__(16) __nv_bfloat16 g_xhi[BATCH * T_SEQ * CDIM];
__device__ __align__(16) __nv_bfloat16 g_xlo[BATCH * T_SEQ * CDIM];
__device__ __align__(16) __nv_bfloat16 g_whi[4 * CDIM * CDIM];
__device__ __align__(16) __nv_bfloat16 g_wlo[4 * CDIM * CDIM];
__device__ __align__(16) __nv_bfloat16 g_yhi[BATCH * T_SEQ * CDIM];
__device__ __align__(16) __nv_bfloat16 g_ylo[BATCH * T_SEQ * CDIM];

// ---------------------------------------------------------------------------
// fp32 -> bf16 hi/lo split conversions (scratch symbols referenced in-kernel;
// NEVER passed as host-side arguments)
// ---------------------------------------------------------------------------
__device__ __forceinline__ void split4(const float* f, __nv_bfloat16* h,
                                       __nv_bfloat16* l) {
#pragma unroll
    for (int j = 0; j < 4; j++) {
        h[j] = __float2bfloat16(f[j]);
        l[j] = __float2bfloat16(f[j] - __bfloat162float(h[j]));
    }
}

__global__ __launch_bounds__(256)
void convert_x(const float* __restrict__ src)
{
    int i = (blockIdx.x * 256 + threadIdx.x) * 4;
    float4 v = *(const float4*)(src + i);
    float f[4] = {v.x, v.y, v.z, v.w};
    __nv_bfloat16 h[4], l[4];
    split4(f, h, l);
    *(uint2*)(g_xhi + i) = *(uint2*)h;
    *(uint2*)(g_xlo + i) = *(uint2*)l;
}

__global__ __launch_bounds__(256)
void convert_y()
{
    int i = (blockIdx.x * 256 + threadIdx.x) * 4;
    float4 v = *(const float4*)(g_y + i);
    float f[4] = {v.x, v.y, v.z, v.w};
    __nv_bfloat16 h[4], l[4];
    split4(f, h, l);
    *(uint2*)(g_yhi + i) = *(uint2*)h;
    *(uint2*)(g_ylo + i) = *(uint2*)l;
}

__global__ __launch_bounds__(256)
void convert_w4(const float* __restrict__ w0, const float* __restrict__ w1,
                const float* __restrict__ w2, const float* __restrict__ w3)
{
    int z = blockIdx.y;
    const float* src = (z == 0) ? w0 : (z == 1) ? w1 : (z == 2) ? w2 : w3;
    int i = (blockIdx.x * 256 + threadIdx.x) * 4;
    float4 v = *(const float4*)(src + i);
    float f[4] = {v.x, v.y, v.z, v.w};
    __nv_bfloat16 h[4], l[4];
    split4(f, h, l);
    size_t o = (size_t)z * CDIM * CDIM + i;
    *(uint2*)(g_whi + o) = *(uint2*)h;
    *(uint2*)(g_wlo + o) = *(uint2*)l;
}

// ---------------------------------------------------------------------------
// Tensor-core GEMM via nvcuda::wmma.
// out[m][n] = sum_k A[m][k]*W[n][k] + bias[n]
// bf16 2-term split: acc = bias + Ahi*Bhi + Ahi*Blo + Alo*Bhi (fp32 accum)
// Block 64x64, BK=32, 128 threads = 4 warps (2x2), warp tile 32x32.
// ---------------------------------------------------------------------------
#define GP 40
#define MAT_H (64 * GP)

template <int MODE>
__global__ __launch_bounds__(128, 4)
void hm_gemm(const float* __restrict__ bias0, const float* __restrict__ bias1,
             const float* __restrict__ bias2, float* __restrict__ out_proj)
{
    __shared__ __align__(32) __nv_bfloat16 sm[4 * MAT_H];
    __shared__ __align__(32) float sbias[16 * 72];

    const int tid = threadIdx.x;
    const int wid = tid >> 5;
    const int wm = wid >> 1, wn = wid & 1;

    const int n0 = blockIdx.x * 64;
    const int m0 = blockIdx.y * 64;
    const int z  = (MODE == 0) ? (int)blockIdx.z : 3;

    const float* bias = (MODE == 0) ? ((z == 0) ? bias0 : (z == 1) ? bias1 : bias2)
                                    : bias0;
    float* outp = (MODE == 0) ? ((z == 0) ? g_q : (z == 1) ? g_k : g_v) : out_proj;

    const __nv_bfloat16* Ahi = ((MODE == 0) ? g_xhi : g_yhi) + (size_t)m0 * CDIM;
    const __nv_bfloat16* Alo = ((MODE == 0) ? g_xlo : g_ylo) + (size_t)m0 * CDIM;
    const __nv_bfloat16* Bhi = g_whi + (size_t)z * CDIM * CDIM + (size_t)n0 * CDIM;
    const __nv_bfloat16* Blo = g_wlo + (size_t)z * CDIM * CDIM + (size_t)n0 * CDIM;
    const __nv_bfloat16* srcs[4] = {Ahi, Alo, Bhi, Blo};

    // bias tile replicated over 16 rows (accumulator initializer)
    for (int idx = tid; idx < 16 * 64; idx += 128) {
        int r = idx >> 6, c = idx & 63;
        sbias[r * 72 + c] = bias[n0 + c];
    }

    // loader: 128 threads, 2 uint4 per thread per matrix (rows 0..63, 32 halves)
    const int lr0 = tid >> 1;
    const int lq0 = (tid & 1) * 2;

    wmma::fragment<wmma::accumulator, 16, 16, 16, float> acc[2][2];
    uint4 pf[4][2];

#pragma unroll
    for (int mat = 0; mat < 4; mat++)
#pragma unroll
        for (int e = 0; e < 2; e++)
            pf[mat][e] = *(const uint4*)(srcs[mat] + (size_t)lr0 * CDIM + (lq0 + e) * 8);

    __syncthreads();  // sbias visible
#pragma unroll
    for (int mi = 0; mi < 2; mi++)
#pragma unroll
        for (int ni = 0; ni < 2; ni++)
            wmma::load_matrix_sync(acc[mi][ni], &sbias[wn * 32 + ni * 16], 72,
                                   wmma::mem_row_major);

    for (int kt = 0; kt < CDIM / 32; kt++) {
        __syncthreads();
#pragma unroll
        for (int mat = 0; mat < 4; mat++)
#pragma unroll
            for (int e = 0; e < 2; e++)
                *(uint4*)(sm + mat * MAT_H + lr0 * GP + (lq0 + e) * 8) = pf[mat][e];
        __syncthreads();

        if (kt < CDIM / 32 - 1) {
            int k0 = (kt + 1) * 32;
#pragma unroll
            for (int mat = 0; mat < 4; mat++)
#pragma unroll
                for (int e = 0; e < 2; e++)
                    pf[mat][e] = *(const uint4*)(srcs[mat] + (size_t)lr0 * CDIM + k0 + (lq0 + e) * 8);
        }

#pragma unroll
        for (int ks = 0; ks < 2; ks++) {
            wmma::fragment<wmma::matrix_a, 16, 16, 16, __nv_bfloat16, wmma::row_major> fah[2], fal[2];
            wmma::fragment<wmma::matrix_b, 16, 16, 16, __nv_bfloat16, wmma::col_major> fbh[2], fbl[2];
#pragma unroll
            for (int mi = 0; mi < 2; mi++) {
                int mr = wm * 32 + mi * 16;
                wmma::load_matrix_sync(fah[mi], &sm[0 * MAT_H + mr * GP + ks * 16], GP);
                wmma::load_matrix_sync(fal[mi], &sm[1 * MAT_H + mr * GP + ks * 16], GP);
            }
#pragma unroll
            for (int ni = 0; ni < 2; ni++) {
                int nr = wn * 32 + ni * 16;
                wmma::load_matrix_sync(fbh[ni], &sm[2 * MAT_H + nr * GP + ks * 16], GP);
                wmma::load_matrix_sync(fbl[ni], &sm[3 * MAT_H + nr * GP + ks * 16], GP);
            }
#pragma unroll
            for (int mi = 0; mi < 2; mi++)
#pragma unroll
                for (int ni = 0; ni < 2; ni++) {
                    wmma::mma_sync(acc[mi][ni], fah[mi], fbh[ni], acc[mi][ni]);
                    wmma::mma_sync(acc[mi][ni], fah[mi], fbl[ni], acc[mi][ni]);
                    wmma::mma_sync(acc[mi][ni], fal[mi], fbh[ni], acc[mi][ni]);
                }
        }
    }

    // epilogue: direct store_matrix_sync to gmem
#pragma unroll
    for (int mi = 0; mi < 2; mi++)
#pragma unroll
        for (int ni = 0; ni < 2; ni++) {
            if (MODE == 0) {
                int b_ = m0 >> 10;
                int t0 = (m0 & 1023) + wm * 32 + mi * 16;
                int h  = n0 >> 6;
                int d0 = wn * 32 + ni * 16;
                float* dst = &outp[(((size_t)(b_ * NH + h)) * T_SEQ + t0) * HDIM + d0];
                wmma::store_matrix_sync(dst, acc[mi][ni], HDIM, wmma::mem_row_major);
            } else {
                int m = m0 + wm * 32 + mi * 16;
                int n = n0 + wn * 32 + ni * 16;
                wmma::store_matrix_sync(&outp[(size_t)m * CDIM + n], acc[mi][ni],
                                        CDIM, wmma::mem_row_major);
            }
        }
}

// ---------------------------------------------------------------------------
// Flash attention (SIMT fp32, proven in R3)
// ---------------------------------------------------------------------------
__global__ __launch_bounds__(256, 1)
void attn_kernel(const float* __restrict__ attn_bias)
{
    extern __shared__ float sh[];
    float* qT = sh;                 // [64][132]
    float* kT = sh + 64 * 132;      // [64][132]
    float* vs = sh + 2 * 64 * 132;  // [128][68]
    float* ps = vs + 128 * 68;      // [128][132]

    const int bh = blockIdx.y;
    const int h  = bh & (NH - 1);
    const int b_ = bh >> 3;
    const int qt = (int)(gridDim.x - 1) - (int)blockIdx.x;
    const int tid = threadIdx.x;
    const int tx = tid & 15;
    const int ty = tid >> 4;

    const float* qg = g_q + (size_t)bh * T_SEQ * HDIM;
    const float* kg = g_k + (size_t)bh * T_SEQ * HDIM;
    const float* vg = g_v + (size_t)bh * T_SEQ * HDIM;
    const float* bias_h = attn_bias + h * 64 * 64;

#pragma unroll
    for (int l = 0; l < 8; l++) {
        int f = tid + l * 256;
        int row = f >> 4, dq = (f & 15) * 4;
        float4 v4 = *(const float4*)&qg[(size_t)(qt * 128 + row) * HDIM + dq];
        qT[(dq + 0) * 132 + row] = v4.x;
        qT[(dq + 1) * 132 + row] = v4.y;
        qT[(dq + 2) * 132 + row] = v4.z;
        qT[(dq + 3) * 132 + row] = v4.w;
    }

    float m_i[8], l_i[8], o[8][4];
#pragma unroll
    for (int i = 0; i < 8; i++) {
        m_i[i] = -1e30f;
        l_i[i] = 0.f;
#pragma unroll
        for (int j = 0; j < 4; j++) o[i][j] = 0.f;
    }

    for (int kt = 0; kt <= qt; kt++) {
        __syncthreads();
#pragma unroll
        for (int l = 0; l < 8; l++) {
            int f = tid + l * 256;
            int row = f >> 4, dq = (f & 15) * 4;
            float4 kv = *(const float4*)&kg[(size_t)(kt * 128 + row) * HDIM + dq];
            kT[(dq + 0) * 132 + row] = kv.x;
            kT[(dq + 1) * 132 + row] = kv.y;
            kT[(dq + 2) * 132 + row] = kv.z;
            kT[(dq + 3) * 132 + row] = kv.w;
            float4 vv = *(const float4*)&vg[(size_t)(kt * 128 + row) * HDIM + dq];
            *(float4*)&vs[row * 68 + dq] = vv;
        }
        float bv = 0.f;
        if (qt < 4 && kt < 4)
            bv = bias_h[(qt * 16 + ty) * 64 + kt * 16 + tx];
        __syncthreads();

        float s[8][8] = {};
#pragma unroll 4
        for (int d = 0; d < 64; d++) {
            float4 a0 = *(const float4*)&qT[d * 132 + ty * 8];
            float4 a1 = *(const float4*)&qT[d * 132 + ty * 8 + 4];
            float4 b0 = *(const float4*)&kT[d * 132 + tx * 8];
            float4 b1 = *(const float4*)&kT[d * 132 + tx * 8 + 4];
            float a[8] = {a0.x, a0.y, a0.z, a0.w, a1.x, a1.y, a1.z, a1.w};
            float b[8] = {b0.x, b0.y, b0.z, b0.w, b1.x, b1.y, b1.z, b1.w};
#pragma unroll
            for (int i = 0; i < 8; i++)
#pragma unroll
                for (int j = 0; j < 8; j++)
                    s[i][j] = fmaf(a[i], b[j], s[i][j]);
        }

#pragma unroll
        for (int i = 0; i < 8; i++)
#pragma unroll
            for (int j = 0; j < 8; j++)
                s[i][j] = s[i][j] * SCALE_F + bv;

        if (tx & 1) {
#pragma unroll
            for (int i = 0; i < 8; i++) s[i][7] = -1e30f;
        }
        if (kt == qt) {
#pragma unroll
            for (int i = 0; i < 8; i++) {
                int qrl = ty * 8 + i;
#pragma unroll
                for (int j = 0; j < 8; j++)
                    if (tx * 8 + j > qrl) s[i][j] = -1e30f;
            }
        }

#pragma unroll
        for (int i = 0; i < 8; i++) {
            float rm = s[i][0];
#pragma unroll
            for (int j = 1; j < 8; j++) rm = fmaxf(rm, s[i][j]);
#pragma unroll
            for (int off = 8; off >= 1; off >>= 1)
                rm = fmaxf(rm, __shfl_xor_sync(0xffffffffu, rm, off));
            float mn = fmaxf(m_i[i], rm);
            float alpha = __expf(m_i[i] - mn);
            float rs = 0.f;
#pragma unroll
            for (int j = 0; j < 8; j++) {
                s[i][j] = __expf(s[i][j] - mn);
                rs += s[i][j];
            }
#pragma unroll
            for (int off = 8; off >= 1; off >>= 1)
                rs += __shfl_xor_sync(0xffffffffu, rs, off);
            l_i[i] = l_i[i] * alpha + rs;
            m_i[i] = mn;
            float4 p0 = {s[i][0], s[i][1], s[i][2], s[i][3]};
            float4 p1 = {s[i][4], s[i][5], s[i][6], s[i][7]};
            *(float4*)&ps[(ty * 8 + i) * 132 + tx * 8]     = p0;
            *(float4*)&ps[(ty * 8 + i) * 132 + tx * 8 + 4] = p1;
#pragma unroll
            for (int j = 0; j < 4; j++) o[i][j] *= alpha;
        }
        __syncthreads();

        for (int k = 0; k < 128; k += 4) {
            float4 v0 = *(const float4*)&vs[(k + 0) * 68 + tx * 4];
            float4 v1 = *(const float4*)&vs[(k + 1) * 68 + tx * 4];
            float4 v2 = *(const float4*)&vs[(k + 2) * 68 + tx * 4];
            float4 v3 = *(const float4*)&vs[(k + 3) * 68 + tx * 4];
#pragma unroll
            for (int i = 0; i < 8; i++) {
                float4 p4 = *(const float4*)&ps[(ty * 8 + i) * 132 + k];
                o[i][0] = fmaf(p4.x, v0.x, o[i][0]);
                o[i][1] = fmaf(p4.x, v0.y, o[i][1]);
                o[i][2] = fmaf(p4.x, v0.z, o[i][2]);
                o[i][3] = fmaf(p4.x, v0.w, o[i][3]);
                o[i][0] = fmaf(p4.y, v1.x, o[i][0]);
                o[i][1] = fmaf(p4.y, v1.y, o[i][1]);
                o[i][2] = fmaf(p4.y, v1.z, o[i][2]);
                o[i][3] = fmaf(p4.y, v1.w, o[i][3]);
                o[i][0] = fmaf(p4.z, v2.x, o[i][0]);
                o[i][1] = fmaf(p4.z, v2.y, o[i][1]);
                o[i][2] = fmaf(p4.z, v2.z, o[i][2]);
                o[i][3] = fmaf(p4.z, v2.w, o[i][3]);
                o[i][0] = fmaf(p4.w, v3.x, o[i][0]);
                o[i][1] = fmaf(p4.w, v3.y, o[i][1]);
                o[i][2] = fmaf(p4.w, v3.z, o[i][2]);
                o[i][3] = fmaf(p4.w, v3.w, o[i][3]);
            }
        }
    }

#pragma unroll
    for (int i = 0; i < 8; i++) {
        float inv = 1.0f / l_i[i];
        int t = qt * 128 + ty * 8 + i;
        float4 r = {o[i][0] * inv, o[i][1] * inv, o[i][2] * inv, o[i][3] * inv};
        *(float4*)&g_y[((size_t)(b_ * T_SEQ + t)) * CDIM + h * 64 + tx * 4] = r;
    }
}

// ---------------------------------------------------------------------------

extern "C" void kernel_launch(void* const* d_in, const int* in_sizes, int n_in,
                              void* d_out, int out_size)
{
    const float* x  = (const float*)d_in[0];
    const float* ab = (const float*)d_in[1];
    const float* Wq = (const float*)d_in[2];
    const float* bq = (const float*)d_in[3];
    const float* Wk = (const float*)d_in[4];
    const float* bk = (const float*)d_in[5];
    const float* Wv = (const float*)d_in[6];
    const float* bv = (const float*)d_in[7];
    const float* Wp = (const float*)d_in[8];
    const float* bp = (const float*)d_in[9];
    float* out = (float*)d_out;

    // bf16 hi/lo conversions (scratch written via device-side symbols only)
    convert_x<<<(BATCH * T_SEQ * CDIM) / 1024, 256>>>(x);
    convert_w4<<<dim3((CDIM * CDIM) / 1024, 4), 256>>>(Wq, Wk, Wv, Wp);

    // QKV projections on tensor cores (wmma)
    hm_gemm<0><<<dim3(CDIM / 64, (BATCH * T_SEQ) / 64, 3), 128>>>(bq, bk, bv, nullptr);

    // Flash attention
    size_t smem = (size_t)(2 * 64 * 132 + 128 * 68 + 128 * 132) * sizeof(float);
    cudaFuncSetAttribute(attn_kernel, cudaFuncAttributeMaxDynamicSharedMemorySize,
                         (int)smem);
    attn_kernel<<<dim3(T_SEQ / 128, BATCH * NH), 256, smem>>>(ab);

    // Output projection
    convert_y<<<(BATCH * T_SEQ * CDIM) / 1024, 256>>>();
    hm_gemm<1><<<dim3(CDIM / 64, (BATCH * T_SEQ) / 64, 1), 128>>>(bp, nullptr, nullptr, out);
}

// round 11
// speedup vs baseline: 2.0756x; 2.0756x over previous
#include <cuda_runtime.h>
#include <cuda_bf16.h>
#include <mma.h>
#include <cstdint>

using namespace nvcuda;

#define BATCH 4
#define T_SEQ 1024
#define CDIM  512
#define NH    8
#define HDIM  64
#define SCALE_F 0.125f

// ---------------------------------------------------------------------------
// Scratch (no cudaMalloc allowed). Referenced ONLY from device code.
// ---------------------------------------------------------------------------
__device__ __align__(16) float g_q[BATCH * NH * T_SEQ * HDIM];
__device__ __align__(16) float g_k[BATCH * NH * T_SEQ * HDIM];
__device__ __align__(16) float g_v[BATCH * NH * T_SEQ * HDIM];
__device__ __align__(16) float g_y[BATCH * T_SEQ * CDIM];

__device__ __align__(16) __nv_bfloat16 g_xhi[BATCH * T_SEQ * CDIM];
__device__ __align__(16) __nv_bfloat16 g_xlo[BATCH * T_SEQ * CDIM];
__device__ __align__(16) __nv_bfloat16 g_whi[4 * CDIM * CDIM];
__device__ __align__(16) __nv_bfloat16 g_wlo[4 * CDIM * CDIM];
__device__ __align__(16) __nv_bfloat16 g_yhi[BATCH * T_SEQ * CDIM];
__device__ __align__(16) __nv_bfloat16 g_ylo[BATCH * T_SEQ * CDIM];

// ---------------------------------------------------------------------------
// helpers
// ---------------------------------------------------------------------------
__device__ __forceinline__ void split4(const float* f, __nv_bfloat16* h,
                                       __nv_bfloat16* l) {
#pragma unroll
    for (int j = 0; j < 4; j++) {
        h[j] = __float2bfloat16(f[j]);
        l[j] = __float2bfloat16(f[j] - __bfloat162float(h[j]));
    }
}

__device__ __forceinline__ void mma_bf16(float* d, const uint32_t* a,
                                         uint32_t b0, uint32_t b1) {
    asm volatile(
        "mma.sync.aligned.m16n8k16.row.col.f32.bf16.bf16.f32 "
        "{%0,%1,%2,%3}, {%4,%5,%6,%7}, {%8,%9}, {%0,%1,%2,%3};"
        : "+f"(d[0]), "+f"(d[1]), "+f"(d[2]), "+f"(d[3])
        : "r"(a[0]), "r"(a[1]), "r"(a[2]), "r"(a[3]), "r"(b0), "r"(b1));
}

__device__ __forceinline__ uint32_t pack_bf2(float lo, float hi) {
    __nv_bfloat162 t = __floats2bfloat162_rn(lo, hi);  // .x=lo (low 16b)
    return *(uint32_t*)&t;
}

// ---------------------------------------------------------------------------
// fp32 -> bf16 hi/lo split conversions (device symbols referenced in-kernel)
// ---------------------------------------------------------------------------
__global__ __launch_bounds__(256)
void convert_x(const float* __restrict__ src)
{
    int i = (blockIdx.x * 256 + threadIdx.x) * 4;
    float4 v = *(const float4*)(src + i);
    float f[4] = {v.x, v.y, v.z, v.w};
    __nv_bfloat16 h[4], l[4];
    split4(f, h, l);
    *(uint2*)(g_xhi + i) = *(uint2*)h;
    *(uint2*)(g_xlo + i) = *(uint2*)l;
}

__global__ __launch_bounds__(256)
void convert_y()
{
    int i = (blockIdx.x * 256 + threadIdx.x) * 4;
    float4 v = *(const float4*)(g_y + i);
    float f[4] = {v.x, v.y, v.z, v.w};
    __nv_bfloat16 h[4], l[4];
    split4(f, h, l);
    *(uint2*)(g_yhi + i) = *(uint2*)h;
    *(uint2*)(g_ylo + i) = *(uint2*)l;
}

__global__ __launch_bounds__(256)
void convert_w4(const float* __restrict__ w0, const float* __restrict__ w1,
                const float* __restrict__ w2, const float* __restrict__ w3)
{
    int z = blockIdx.y;
    const float* src = (z == 0) ? w0 : (z == 1) ? w1 : (z == 2) ? w2 : w3;
    int i = (blockIdx.x * 256 + threadIdx.x) * 4;
    float4 v = *(const float4*)(src + i);
    float f[4] = {v.x, v.y, v.z, v.w};
    __nv_bfloat16 h[4], l[4];
    split4(f, h, l);
    size_t o = (size_t)z * CDIM * CDIM + i;
    *(uint2*)(g_whi + o) = *(uint2*)h;
    *(uint2*)(g_wlo + o) = *(uint2*)l;
}

// ---------------------------------------------------------------------------
// Projection GEMMs via wmma (passing R10 version, unchanged)
// ---------------------------------------------------------------------------
#define GP 40
#define MAT_H (64 * GP)

template <int MODE>
__global__ __launch_bounds__(128, 4)
void hm_gemm(const float* __restrict__ bias0, const float* __restrict__ bias1,
             const float* __restrict__ bias2, float* __restrict__ out_proj)
{
    __shared__ __align__(32) __nv_bfloat16 sm[4 * MAT_H];
    __shared__ __align__(32) float sbias[16 * 72];

    const int tid = threadIdx.x;
    const int wid = tid >> 5;
    const int wm = wid >> 1, wn = wid & 1;

    const int n0 = blockIdx.x * 64;
    const int m0 = blockIdx.y * 64;
    const int z  = (MODE == 0) ? (int)blockIdx.z : 3;

    const float* bias = (MODE == 0) ? ((z == 0) ? bias0 : (z == 1) ? bias1 : bias2)
                                    : bias0;
    float* outp = (MODE == 0) ? ((z == 0) ? g_q : (z == 1) ? g_k : g_v) : out_proj;

    const __nv_bfloat16* Ahi = ((MODE == 0) ? g_xhi : g_yhi) + (size_t)m0 * CDIM;
    const __nv_bfloat16* Alo = ((MODE == 0) ? g_xlo : g_ylo) + (size_t)m0 * CDIM;
    const __nv_bfloat16* Bhi = g_whi + (size_t)z * CDIM * CDIM + (size_t)n0 * CDIM;
    const __nv_bfloat16* Blo = g_wlo + (size_t)z * CDIM * CDIM + (size_t)n0 * CDIM;
    const __nv_bfloat16* srcs[4] = {Ahi, Alo, Bhi, Blo};

    for (int idx = tid; idx < 16 * 64; idx += 128) {
        int r = idx >> 6, c = idx & 63;
        sbias[r * 72 + c] = bias[n0 + c];
    }

    const int lr0 = tid >> 1;
    const int lq0 = (tid & 1) * 2;

    wmma::fragment<wmma::accumulator, 16, 16, 16, float> acc[2][2];
    uint4 pf[4][2];

#pragma unroll
    for (int mat = 0; mat < 4; mat++)
#pragma unroll
        for (int e = 0; e < 2; e++)
            pf[mat][e] = *(const uint4*)(srcs[mat] + (size_t)lr0 * CDIM + (lq0 + e) * 8);

    __syncthreads();
#pragma unroll
    for (int mi = 0; mi < 2; mi++)
#pragma unroll
        for (int ni = 0; ni < 2; ni++)
            wmma::load_matrix_sync(acc[mi][ni], &sbias[wn * 32 + ni * 16], 72,
                                   wmma::mem_row_major);

    for (int kt = 0; kt < CDIM / 32; kt++) {
        __syncthreads();
#pragma unroll
        for (int mat = 0; mat < 4; mat++)
#pragma unroll
            for (int e = 0; e < 2; e++)
                *(uint4*)(sm + mat * MAT_H + lr0 * GP + (lq0 + e) * 8) = pf[mat][e];
        __syncthreads();

        if (kt < CDIM / 32 - 1) {
            int k0 = (kt + 1) * 32;
#pragma unroll
            for (int mat = 0; mat < 4; mat++)
#pragma unroll
                for (int e = 0; e < 2; e++)
                    pf[mat][e] = *(const uint4*)(srcs[mat] + (size_t)lr0 * CDIM + k0 + (lq0 + e) * 8);
        }

#pragma unroll
        for (int ks = 0; ks < 2; ks++) {
            wmma::fragment<wmma::matrix_a, 16, 16, 16, __nv_bfloat16, wmma::row_major> fah[2], fal[2];
            wmma::fragment<wmma::matrix_b, 16, 16, 16, __nv_bfloat16, wmma::col_major> fbh[2], fbl[2];
#pragma unroll
            for (int mi = 0; mi < 2; mi++) {
                int mr = wm * 32 + mi * 16;
                wmma::load_matrix_sync(fah[mi], &sm[0 * MAT_H + mr * GP + ks * 16], GP);
                wmma::load_matrix_sync(fal[mi], &sm[1 * MAT_H + mr * GP + ks * 16], GP);
            }
#pragma unroll
            for (int ni = 0; ni < 2; ni++) {
                int nr = wn * 32 + ni * 16;
                wmma::load_matrix_sync(fbh[ni], &sm[2 * MAT_H + nr * GP + ks * 16], GP);
                wmma::load_matrix_sync(fbl[ni], &sm[3 * MAT_H + nr * GP + ks * 16], GP);
            }
#pragma unroll
            for (int mi = 0; mi < 2; mi++)
#pragma unroll
                for (int ni = 0; ni < 2; ni++) {
                    wmma::mma_sync(acc[mi][ni], fah[mi], fbh[ni], acc[mi][ni]);
                    wmma::mma_sync(acc[mi][ni], fah[mi], fbl[ni], acc[mi][ni]);
                    wmma::mma_sync(acc[mi][ni], fal[mi], fbh[ni], acc[mi][ni]);
                }
        }
    }

#pragma unroll
    for (int mi = 0; mi < 2; mi++)
#pragma unroll
        for (int ni = 0; ni < 2; ni++) {
            if (MODE == 0) {
                int b_ = m0 >> 10;
                int t0 = (m0 & 1023) + wm * 32 + mi * 16;
                int h  = n0 >> 6;
                int d0 = wn * 32 + ni * 16;
                float* dst = &outp[(((size_t)(b_ * NH + h)) * T_SEQ + t0) * HDIM + d0];
                wmma::store_matrix_sync(dst, acc[mi][ni], HDIM, wmma::mem_row_major);
            } else {
                int m = m0 + wm * 32 + mi * 16;
                int n = n0 + wn * 32 + ni * 16;
                wmma::store_matrix_sync(&outp[(size_t)m * CDIM + n], acc[mi][ni],
                                        CDIM, wmma::mem_row_major);
            }
        }
}

// ---------------------------------------------------------------------------
// Flash attention on mma.sync (m16n8k16, bf16 hi/lo split, fp32 softmax)
// Block: (b,h) x 128-row q tile; 8 warps; warp = 16-row strip.
// K tile = 64 keys staged hi/lo; V staged transposed [d][key] hi/lo.
// ---------------------------------------------------------------------------
#define KP 72                      // smem pitch in halves
#define FA_SMEM (36864 * 2 + 4096) // Q(or K+V) halves + bias floats

__global__ __launch_bounds__(256, 1)
void fa_kernel(const float* __restrict__ attn_bias)
{
    extern __shared__ char fsh[];
    __nv_bfloat16* sA    = (__nv_bfloat16*)fsh;      // 36864 halves
    float*         sbias = (float*)(fsh + 36864 * 2);

    const int bh = blockIdx.y;
    const int h  = bh & (NH - 1);
    const int b_ = bh >> 3;
    const int qt = (int)(gridDim.x - 1) - (int)blockIdx.x;  // heavy first
    const int tid = threadIdx.x;
    const int w   = tid >> 5, lane = tid & 31;
    const int gid = lane >> 2, tig = lane & 3;

    const float* qg = g_q + (size_t)bh * T_SEQ * HDIM + (size_t)qt * 128 * HDIM;
    const float* kg = g_k + (size_t)bh * T_SEQ * HDIM;
    const float* vg = g_v + (size_t)bh * T_SEQ * HDIM;

    // ---- stage Q (128 x 64) as hi/lo bf16 [row][KP] ----
    for (int i = tid; i < 128 * 16; i += 256) {
        int row = i >> 4, c4 = (i & 15) * 4;
        float4 v = *(const float4*)&qg[(size_t)row * HDIM + c4];
        float f[4] = {v.x, v.y, v.z, v.w};
        __nv_bfloat16 hh[4], ll[4];
        split4(f, hh, ll);
#pragma unroll
        for (int j = 0; j < 4; j++) {
            sA[row * KP + c4 + j]        = hh[j];
            sA[9216 + row * KP + c4 + j] = ll[j];
        }
    }
    if (qt < 4) {
        const float* bsrc = attn_bias + h * 64 * 64 + (qt * 16) * 64;
        for (int i = tid; i < 16 * 64; i += 256) sbias[i] = bsrc[i];
    }
    __syncthreads();

    // ---- load Q fragments (resident) ----
    uint32_t qh[4][4], ql[4][4];
    const int qrl = w * 16 + gid;
#pragma unroll
    for (int ks = 0; ks < 4; ks++) {
        int ad = qrl * KP + ks * 16 + 2 * tig;
        qh[ks][0] = *(const uint32_t*)&sA[ad];
        qh[ks][1] = *(const uint32_t*)&sA[ad + 8 * KP];
        qh[ks][2] = *(const uint32_t*)&sA[ad + 8];
        qh[ks][3] = *(const uint32_t*)&sA[ad + 8 * KP + 8];
        ql[ks][0] = *(const uint32_t*)&sA[9216 + ad];
        ql[ks][1] = *(const uint32_t*)&sA[9216 + ad + 8 * KP];
        ql[ks][2] = *(const uint32_t*)&sA[9216 + ad + 8];
        ql[ks][3] = *(const uint32_t*)&sA[9216 + ad + 8 * KP + 8];
    }
    __syncthreads();   // Q fragments extracted; sA reused for K/V

    __nv_bfloat16* skh = sA;
    __nv_bfloat16* skl = sA + 4608;
    __nv_bfloat16* svh = sA + 9216;
    __nv_bfloat16* svl = sA + 13824;

    float m0 = -1e30f, m1 = -1e30f, l0 = 0.f, l1 = 0.f;
    float oacc[8][4] = {};
    const int qr0 = qt * 128 + w * 16 + gid;
    const int qr1 = qr0 + 8;
    const int ktmax = 2 * qt + 1;

    for (int kt = 0; kt <= ktmax; kt++) {
        __syncthreads();
        // stage K [key][KP] and V transposed [d][KP] (hi/lo)
        for (int i = tid; i < 64 * 16; i += 256) {
            int row = i >> 4, c4 = (i & 15) * 4;
            float4 kv = *(const float4*)&kg[(size_t)(kt * 64 + row) * HDIM + c4];
            float fk[4] = {kv.x, kv.y, kv.z, kv.w};
            __nv_bfloat16 hh[4], ll[4];
            split4(fk, hh, ll);
#pragma unroll
            for (int j = 0; j < 4; j++) {
                skh[row * KP + c4 + j] = hh[j];
                skl[row * KP + c4 + j] = ll[j];
            }
            float4 vv = *(const float4*)&vg[(size_t)(kt * 64 + row) * HDIM + c4];
            float fv[4] = {vv.x, vv.y, vv.z, vv.w};
            split4(fv, hh, ll);
#pragma unroll
            for (int j = 0; j < 4; j++) {
                svh[(c4 + j) * KP + row] = hh[j];
                svl[(c4 + j) * KP + row] = ll[j];
            }
        }
        __syncthreads();

        if (kt * 64 > qt * 128 + w * 16 + 15) continue;  // fully masked strip

        // ---- S = Q K^T (16 x 64 per warp), bf16 2-term split ----
        float sacc[8][4] = {};
#pragma unroll
        for (int nt = 0; nt < 8; nt++)
#pragma unroll
            for (int ks = 0; ks < 4; ks++) {
                int ad = (nt * 8 + gid) * KP + ks * 16 + 2 * tig;
                uint32_t bh0 = *(const uint32_t*)&skh[ad];
                uint32_t bh1 = *(const uint32_t*)&skh[ad + 8];
                uint32_t bl0 = *(const uint32_t*)&skl[ad];
                uint32_t bl1 = *(const uint32_t*)&skl[ad + 8];
                mma_bf16(sacc[nt], qh[ks], bh0, bh1);
                mma_bf16(sacc[nt], qh[ks], bl0, bl1);
                mma_bf16(sacc[nt], ql[ks], bh0, bh1);
            }

        // ---- scale + bias + masks ----
#pragma unroll
        for (int nt = 0; nt < 8; nt++) {
            float bb0 = 0.f, bb1 = 0.f;
            if (qt < 4) {
                bb0 = sbias[(2 * w) * 64 + kt * 8 + nt];
                bb1 = sbias[(2 * w + 1) * 64 + kt * 8 + nt];
            }
#pragma unroll
            for (int c = 0; c < 4; c++) {
                int kcol = kt * 64 + nt * 8 + 2 * tig + (c & 1);
                int qr   = (c < 2) ? qr0 : qr1;
                float s  = sacc[nt][c] * SCALE_F + ((c < 2) ? bb0 : bb1);
                if (kcol > qr || (kcol & 15) == 15) s = -1e30f;
                sacc[nt][c] = s;
            }
        }

        // ---- online softmax (rows qr0: c0,c1 / qr1: c2,c3; quad = lanes w/ same gid) ----
        float rm0 = -1e30f, rm1 = -1e30f;
#pragma unroll
        for (int nt = 0; nt < 8; nt++) {
            rm0 = fmaxf(rm0, fmaxf(sacc[nt][0], sacc[nt][1]));
            rm1 = fmaxf(rm1, fmaxf(sacc[nt][2], sacc[nt][3]));
        }
        rm0 = fmaxf(rm0, __shfl_xor_sync(0xffffffffu, rm0, 1));
        rm0 = fmaxf(rm0, __shfl_xor_sync(0xffffffffu, rm0, 2));
        rm1 = fmaxf(rm1, __shfl_xor_sync(0xffffffffu, rm1, 1));
        rm1 = fmaxf(rm1, __shfl_xor_sync(0xffffffffu, rm1, 2));
        float mn0 = fmaxf(m0, rm0), mn1 = fmaxf(m1, rm1);
        float a0 = __expf(m0 - mn0), a1 = __expf(m1 - mn1);
        float rs0 = 0.f, rs1 = 0.f;
#pragma unroll
        for (int nt = 0; nt < 8; nt++) {
            sacc[nt][0] = __expf(sacc[nt][0] - mn0);
            sacc[nt][1] = __expf(sacc[nt][1] - mn0);
            sacc[nt][2] = __expf(sacc[nt][2] - mn1);
            sacc[nt][3] = __expf(sacc[nt][3] - mn1);
            rs0 += sacc[nt][0] + sacc[nt][1];
            rs1 += sacc[nt][2] + sacc[nt][3];
        }
        rs0 += __shfl_xor_sync(0xffffffffu, rs0, 1);
        rs0 += __shfl_xor_sync(0xffffffffu, rs0, 2);
        rs1 += __shfl_xor_sync(0xffffffffu, rs1, 1);
        rs1 += __shfl_xor_sync(0xffffffffu, rs1, 2);
        l0 = l0 * a0 + rs0; m0 = mn0;
        l1 = l1 * a1 + rs1; m1 = mn1;
#pragma unroll
        for (int dt = 0; dt < 8; dt++) {
            oacc[dt][0] *= a0; oacc[dt][1] *= a0;
            oacc[dt][2] *= a1; oacc[dt][3] *= a1;
        }

        // ---- P -> A-fragments directly from S accumulators (hi/lo split) ----
        uint32_t ph[4][4], pl[4][4];
#pragma unroll
        for (int ks = 0; ks < 4; ks++) {
#pragma unroll
            for (int half = 0; half < 2; half++) {   // tiles 2ks, 2ks+1
                int nt = 2 * ks + half;
#pragma unroll
                for (int rr = 0; rr < 2; rr++) {     // rows gid / gid+8
                    float pe = sacc[nt][rr * 2 + 0];
                    float po = sacc[nt][rr * 2 + 1];
                    float he = __bfloat162float(__float2bfloat16(pe));
                    float ho = __bfloat162float(__float2bfloat16(po));
                    ph[ks][half * 2 + rr] = pack_bf2(he, ho);
                    pl[ks][half * 2 + rr] = pack_bf2(pe - he, po - ho);
                }
            }
        }
        // reorder: a-frag index mapping = {r0k0, r1k0, r0k8, r1k8}
        // built above as [half*2+rr]: half0 -> k 2tig (a0,a1), half1 -> k 2tig+8 (a2,a3) ✓

        // ---- O += P V ----
#pragma unroll
        for (int dt = 0; dt < 8; dt++)
#pragma unroll
            for (int ks = 0; ks < 4; ks++) {
                int ad = (dt * 8 + gid) * KP + ks * 16 + 2 * tig;
                uint32_t vh0 = *(const uint32_t*)&svh[ad];
                uint32_t vh1 = *(const uint32_t*)&svh[ad + 8];
                uint32_t vl0 = *(const uint32_t*)&svl[ad];
                uint32_t vl1 = *(const uint32_t*)&svl[ad + 8];
                mma_bf16(oacc[dt], ph[ks], vh0, vh1);
                mma_bf16(oacc[dt], ph[ks], vl0, vl1);
                mma_bf16(oacc[dt], pl[ks], vh0, vh1);
            }
    }

    // ---- epilogue: y[b][t][h*64+d] ----
    float inv0 = 1.0f / l0, inv1 = 1.0f / l1;
#pragma unroll
    for (int dt = 0; dt < 8; dt++) {
        int dcol = h * 64 + dt * 8 + 2 * tig;
        float2 r0 = {oacc[dt][0] * inv0, oacc[dt][1] * inv0};
        float2 r1 = {oacc[dt][2] * inv1, oacc[dt][3] * inv1};
        *(float2*)&g_y[((size_t)(b_ * T_SEQ + qr0)) * CDIM + dcol] = r0;
        *(float2*)&g_y[((size_t)(b_ * T_SEQ + qr1)) * CDIM + dcol] = r1;
    }
}

// ---------------------------------------------------------------------------

extern "C" void kernel_launch(void* const* d_in, const int* in_sizes, int n_in,
                              void* d_out, int out_size)
{
    const float* x  = (const float*)d_in[0];
    const float* ab = (const float*)d_in[1];
    const float* Wq = (const float*)d_in[2];
    const float* bq = (const float*)d_in[3];
    const float* Wk = (const float*)d_in[4];
    const float* bk = (const float*)d_in[5];
    const float* Wv = (const float*)d_in[6];
    const float* bv = (const float*)d_in[7];
    const float* Wp = (const float*)d_in[8];
    const float* bp = (const float*)d_in[9];
    float* out = (float*)d_out;

    // bf16 hi/lo conversions
    convert_x<<<(BATCH * T_SEQ * CDIM) / 1024, 256>>>(x);
    convert_w4<<<dim3((CDIM * CDIM) / 1024, 4), 256>>>(Wq, Wk, Wv, Wp);

    // QKV projections (wmma)
    hm_gemm<0><<<dim3(CDIM / 64, (BATCH * T_SEQ) / 64, 3), 128>>>(bq, bk, bv, nullptr);

    // Flash attention (mma.sync)
    cudaFuncSetAttribute(fa_kernel, cudaFuncAttributeMaxDynamicSharedMemorySize,
                         FA_SMEM);
    fa_kernel<<<dim3(T_SEQ / 128, BATCH * NH), 256, FA_SMEM>>>(ab);

    // Output projection
    convert_y<<<(BATCH * T_SEQ * CDIM) / 1024, 256>>>();
    hm_gemm<1><<<dim3(CDIM / 64, (BATCH * T_SEQ) / 64, 1), 128>>>(bp, nullptr, nullptr, out);
}

// round 12
// speedup vs baseline: 2.1237x; 1.0232x over previous
#include <cuda_runtime.h>
#include <cuda_bf16.h>
#include <mma.h>
#include <cstdint>

using namespace nvcuda;

#define BATCH 4
#define T_SEQ 1024
#define CDIM  512
#define NH    8
#define HDIM  64
#define SCALE_F 0.125f

// ---------------------------------------------------------------------------
// Scratch (no cudaMalloc allowed). Referenced ONLY from device code.
// ---------------------------------------------------------------------------
__device__ __align__(16) float g_q[BATCH * NH * T_SEQ * HDIM];
__device__ __align__(16) float g_k[BATCH * NH * T_SEQ * HDIM];
__device__ __align__(16) float g_v[BATCH * NH * T_SEQ * HDIM];

__device__ __align__(16) __nv_bfloat16 g_xhi[BATCH * T_SEQ * CDIM];
__device__ __align__(16) __nv_bfloat16 g_xlo[BATCH * T_SEQ * CDIM];
__device__ __align__(16) __nv_bfloat16 g_whi[4 * CDIM * CDIM];
__device__ __align__(16) __nv_bfloat16 g_wlo[4 * CDIM * CDIM];
__device__ __align__(16) __nv_bfloat16 g_yhi[BATCH * T_SEQ * CDIM];
__device__ __align__(16) __nv_bfloat16 g_ylo[BATCH * T_SEQ * CDIM];

// K/V in MMA-ready bf16 hi/lo form; V pre-transposed [bh][d][t]
__device__ __align__(16) __nv_bfloat16 g_khi[BATCH * NH * T_SEQ * HDIM];
__device__ __align__(16) __nv_bfloat16 g_klo[BATCH * NH * T_SEQ * HDIM];
__device__ __align__(16) __nv_bfloat16 g_vhi[BATCH * NH * HDIM * T_SEQ];
__device__ __align__(16) __nv_bfloat16 g_vlo[BATCH * NH * HDIM * T_SEQ];

// ---------------------------------------------------------------------------
// helpers
// ---------------------------------------------------------------------------
__device__ __forceinline__ void split4(const float* f, __nv_bfloat16* h,
                                       __nv_bfloat16* l) {
#pragma unroll
    for (int j = 0; j < 4; j++) {
        h[j] = __float2bfloat16(f[j]);
        l[j] = __float2bfloat16(f[j] - __bfloat162float(h[j]));
    }
}

__device__ __forceinline__ void mma_bf16(float* d, const uint32_t* a,
                                         uint32_t b0, uint32_t b1) {
    asm volatile(
        "mma.sync.aligned.m16n8k16.row.col.f32.bf16.bf16.f32 "
        "{%0,%1,%2,%3}, {%4,%5,%6,%7}, {%8,%9}, {%0,%1,%2,%3};"
        : "+f"(d[0]), "+f"(d[1]), "+f"(d[2]), "+f"(d[3])
        : "r"(a[0]), "r"(a[1]), "r"(a[2]), "r"(a[3]), "r"(b0), "r"(b1));
}

__device__ __forceinline__ uint32_t pack_bf2(float lo, float hi) {
    __nv_bfloat162 t = __floats2bfloat162_rn(lo, hi);  // .x = low 16 bits
    return *(uint32_t*)&t;
}

// ---------------------------------------------------------------------------
// fp32 -> bf16 hi/lo split conversions
// ---------------------------------------------------------------------------
__global__ __launch_bounds__(256)
void convert_x(const float* __restrict__ src)
{
    int i = (blockIdx.x * 256 + threadIdx.x) * 4;
    float4 v = *(const float4*)(src + i);
    float f[4] = {v.x, v.y, v.z, v.w};
    __nv_bfloat16 h[4], l[4];
    split4(f, h, l);
    *(uint2*)(g_xhi + i) = *(uint2*)h;
    *(uint2*)(g_xlo + i) = *(uint2*)l;
}

__global__ __launch_bounds__(256)
void convert_w4(const float* __restrict__ w0, const float* __restrict__ w1,
                const float* __restrict__ w2, const float* __restrict__ w3)
{
    int z = blockIdx.y;
    const float* src = (z == 0) ? w0 : (z == 1) ? w1 : (z == 2) ? w2 : w3;
    int i = (blockIdx.x * 256 + threadIdx.x) * 4;
    float4 v = *(const float4*)(src + i);
    float f[4] = {v.x, v.y, v.z, v.w};
    __nv_bfloat16 h[4], l[4];
    split4(f, h, l);
    size_t o = (size_t)z * CDIM * CDIM + i;
    *(uint2*)(g_whi + o) = *(uint2*)h;
    *(uint2*)(g_wlo + o) = *(uint2*)l;
}

// K -> khi/klo [bh][t][d];  V -> vhi/vlo transposed [bh][d][t]
__global__ __launch_bounds__(256)
void convert_kv()
{
    __shared__ float vt[64][68];

    const int bh = blockIdx.y;
    const int t0 = blockIdx.x * 64;
    const int tid = threadIdx.x;
    const size_t base = (size_t)bh * T_SEQ * HDIM;

    // K: straight-through split (coalesced both sides)
    for (int i = tid; i < 64 * 16; i += 256) {
        int row = i >> 4, c4 = (i & 15) * 4;
        size_t idx = base + (size_t)(t0 + row) * HDIM + c4;
        float4 v = *(const float4*)&g_k[idx];
        float f[4] = {v.x, v.y, v.z, v.w};
        __nv_bfloat16 h[4], l[4];
        split4(f, h, l);
        *(uint2*)(g_khi + idx) = *(uint2*)h;
        *(uint2*)(g_klo + idx) = *(uint2*)l;
        // stage V tile for transpose
        float4 vv = *(const float4*)&g_v[idx];
        vt[row][c4 + 0] = vv.x; vt[row][c4 + 1] = vv.y;
        vt[row][c4 + 2] = vv.z; vt[row][c4 + 3] = vv.w;
    }
    __syncthreads();

    // V: transposed write [d][t]
    for (int i = tid; i < 64 * 16; i += 256) {
        int d = i >> 4, tq = (i & 15) * 4;
        float f[4] = {vt[tq][d], vt[tq + 1][d], vt[tq + 2][d], vt[tq + 3][d]};
        __nv_bfloat16 h[4], l[4];
        split4(f, h, l);
        size_t idx = (size_t)bh * HDIM * T_SEQ + (size_t)d * T_SEQ + t0 + tq;
        *(uint2*)(g_vhi + idx) = *(uint2*)h;
        *(uint2*)(g_vlo + idx) = *(uint2*)l;
    }
}

// ---------------------------------------------------------------------------
// Projection GEMMs via wmma (passing R10 version, unchanged)
// ---------------------------------------------------------------------------
#define GP 40
#define MAT_H (64 * GP)

template <int MODE>
__global__ __launch_bounds__(128, 4)
void hm_gemm(const float* __restrict__ bias0, const float* __restrict__ bias1,
             const float* __restrict__ bias2, float* __restrict__ out_proj)
{
    __shared__ __align__(32) __nv_bfloat16 sm[4 * MAT_H];
    __shared__ __align__(32) float sbias[16 * 72];

    const int tid = threadIdx.x;
    const int wid = tid >> 5;
    const int wm = wid >> 1, wn = wid & 1;

    const int n0 = blockIdx.x * 64;
    const int m0 = blockIdx.y * 64;
    const int z  = (MODE == 0) ? (int)blockIdx.z : 3;

    const float* bias = (MODE == 0) ? ((z == 0) ? bias0 : (z == 1) ? bias1 : bias2)
                                    : bias0;
    float* outp = (MODE == 0) ? ((z == 0) ? g_q : (z == 1) ? g_k : g_v) : out_proj;

    const __nv_bfloat16* Ahi = ((MODE == 0) ? g_xhi : g_yhi) + (size_t)m0 * CDIM;
    const __nv_bfloat16* Alo = ((MODE == 0) ? g_xlo : g_ylo) + (size_t)m0 * CDIM;
    const __nv_bfloat16* Bhi = g_whi + (size_t)z * CDIM * CDIM + (size_t)n0 * CDIM;
    const __nv_bfloat16* Blo = g_wlo + (size_t)z * CDIM * CDIM + (size_t)n0 * CDIM;
    const __nv_bfloat16* srcs[4] = {Ahi, Alo, Bhi, Blo};

    for (int idx = tid; idx < 16 * 64; idx += 128) {
        int r = idx >> 6, c = idx & 63;
        sbias[r * 72 + c] = bias[n0 + c];
    }

    const int lr0 = tid >> 1;
    const int lq0 = (tid & 1) * 2;

    wmma::fragment<wmma::accumulator, 16, 16, 16, float> acc[2][2];
    uint4 pf[4][2];

#pragma unroll
    for (int mat = 0; mat < 4; mat++)
#pragma unroll
        for (int e = 0; e < 2; e++)
            pf[mat][e] = *(const uint4*)(srcs[mat] + (size_t)lr0 * CDIM + (lq0 + e) * 8);

    __syncthreads();
#pragma unroll
    for (int mi = 0; mi < 2; mi++)
#pragma unroll
        for (int ni = 0; ni < 2; ni++)
            wmma::load_matrix_sync(acc[mi][ni], &sbias[wn * 32 + ni * 16], 72,
                                   wmma::mem_row_major);

    for (int kt = 0; kt < CDIM / 32; kt++) {
        __syncthreads();
#pragma unroll
        for (int mat = 0; mat < 4; mat++)
#pragma unroll
            for (int e = 0; e < 2; e++)
                *(uint4*)(sm + mat * MAT_H + lr0 * GP + (lq0 + e) * 8) = pf[mat][e];
        __syncthreads();

        if (kt < CDIM / 32 - 1) {
            int k0 = (kt + 1) * 32;
#pragma unroll
            for (int mat = 0; mat < 4; mat++)
#pragma unroll
                for (int e = 0; e < 2; e++)
                    pf[mat][e] = *(const uint4*)(srcs[mat] + (size_t)lr0 * CDIM + k0 + (lq0 + e) * 8);
        }

#pragma unroll
        for (int ks = 0; ks < 2; ks++) {
            wmma::fragment<wmma::matrix_a, 16, 16, 16, __nv_bfloat16, wmma::row_major> fah[2], fal[2];
            wmma::fragment<wmma::matrix_b, 16, 16, 16, __nv_bfloat16, wmma::col_major> fbh[2], fbl[2];
#pragma unroll
            for (int mi = 0; mi < 2; mi++) {
                int mr = wm * 32 + mi * 16;
                wmma::load_matrix_sync(fah[mi], &sm[0 * MAT_H + mr * GP + ks * 16], GP);
                wmma::load_matrix_sync(fal[mi], &sm[1 * MAT_H + mr * GP + ks * 16], GP);
            }
#pragma unroll
            for (int ni = 0; ni < 2; ni++) {
                int nr = wn * 32 + ni * 16;
                wmma::load_matrix_sync(fbh[ni], &sm[2 * MAT_H + nr * GP + ks * 16], GP);
                wmma::load_matrix_sync(fbl[ni], &sm[3 * MAT_H + nr * GP + ks * 16], GP);
            }
#pragma unroll
            for (int mi = 0; mi < 2; mi++)
#pragma unroll
                for (int ni = 0; ni < 2; ni++) {
                    wmma::mma_sync(acc[mi][ni], fah[mi], fbh[ni], acc[mi][ni]);
                    wmma::mma_sync(acc[mi][ni], fah[mi], fbl[ni], acc[mi][ni]);
                    wmma::mma_sync(acc[mi][ni], fal[mi], fbh[ni], acc[mi][ni]);
                }
        }
    }

#pragma unroll
    for (int mi = 0; mi < 2; mi++)
#pragma unroll
        for (int ni = 0; ni < 2; ni++) {
            if (MODE == 0) {
                int b_ = m0 >> 10;
                int t0 = (m0 & 1023) + wm * 32 + mi * 16;
                int h  = n0 >> 6;
                int d0 = wn * 32 + ni * 16;
                float* dst = &outp[(((size_t)(b_ * NH + h)) * T_SEQ + t0) * HDIM + d0];
                wmma::store_matrix_sync(dst, acc[mi][ni], HDIM, wmma::mem_row_major);
            } else {
                int m = m0 + wm * 32 + mi * 16;
                int n = n0 + wn * 32 + ni * 16;
                wmma::store_matrix_sync(&outp[(size_t)m * CDIM + n], acc[mi][ni],
                                        CDIM, wmma::mem_row_major);
            }
        }
}

// ---------------------------------------------------------------------------
// Flash attention on mma.sync; K/V staged from pre-converted bf16 buffers,
// double-buffered (one __syncthreads per kt iteration).
// ---------------------------------------------------------------------------
#define KP 72                         // smem pitch in halves
#define BUF_H 18432                   // halves per K/V buffer (4 arrays x 4608)
#define FA_SMEM (2 * BUF_H * 2 + 4096)

__global__ __launch_bounds__(256, 1)
void fa_kernel(const float* __restrict__ attn_bias)
{
    extern __shared__ char fsh[];
    __nv_bfloat16* sA    = (__nv_bfloat16*)fsh;       // 2 x BUF_H halves
    float*         sbias = (float*)(fsh + 2 * BUF_H * 2);

    const int bh = blockIdx.y;
    const int h  = bh & (NH - 1);
    const int b_ = bh >> 3;
    const int qt = (int)(gridDim.x - 1) - (int)blockIdx.x;  // heavy first
    const int tid = threadIdx.x;
    const int w   = tid >> 5, lane = tid & 31;
    const int gid = lane >> 2, tig = lane & 3;

    const float* qg = g_q + (size_t)bh * T_SEQ * HDIM + (size_t)qt * 128 * HDIM;
    const __nv_bfloat16* khg = g_khi + (size_t)bh * T_SEQ * HDIM;
    const __nv_bfloat16* klg = g_klo + (size_t)bh * T_SEQ * HDIM;
    const __nv_bfloat16* vhg = g_vhi + (size_t)bh * HDIM * T_SEQ;
    const __nv_bfloat16* vlg = g_vlo + (size_t)bh * HDIM * T_SEQ;

    // ---- stage Q (128 x 64) hi/lo into buffer 0 region ----
    for (int i = tid; i < 128 * 16; i += 256) {
        int row = i >> 4, c4 = (i & 15) * 4;
        float4 v = *(const float4*)&qg[(size_t)row * HDIM + c4];
        float f[4] = {v.x, v.y, v.z, v.w};
        __nv_bfloat16 hh[4], ll[4];
        split4(f, hh, ll);
#pragma unroll
        for (int j = 0; j < 4; j++) {
            sA[row * KP + c4 + j]        = hh[j];
            sA[9216 + row * KP + c4 + j] = ll[j];
        }
    }
    if (qt < 4) {
        const float* bsrc = attn_bias + h * 64 * 64 + (qt * 16) * 64;
        for (int i = tid; i < 16 * 64; i += 256) sbias[i] = bsrc[i];
    }
    __syncthreads();

    // ---- Q fragments (resident) ----
    uint32_t qh[4][4], ql[4][4];
    const int qrl = w * 16 + gid;
#pragma unroll
    for (int ks = 0; ks < 4; ks++) {
        int ad = qrl * KP + ks * 16 + 2 * tig;
        qh[ks][0] = *(const uint32_t*)&sA[ad];
        qh[ks][1] = *(const uint32_t*)&sA[ad + 8 * KP];
        qh[ks][2] = *(const uint32_t*)&sA[ad + 8];
        qh[ks][3] = *(const uint32_t*)&sA[ad + 8 * KP + 8];
        ql[ks][0] = *(const uint32_t*)&sA[9216 + ad];
        ql[ks][1] = *(const uint32_t*)&sA[9216 + ad + 8 * KP];
        ql[ks][2] = *(const uint32_t*)&sA[9216 + ad + 8];
        ql[ks][3] = *(const uint32_t*)&sA[9216 + ad + 8 * KP + 8];
    }
    __syncthreads();   // Q extracted; smem reused for K/V double buffer

    const int ktmax = 2 * qt + 1;
    // copy-stage lambda replacement (macro-ish): row = i>>3, seg = i&7
    // K hi/lo: [key][d]; V hi/lo: [d][key] (pre-transposed in gmem)
    const int crow = tid >> 1;          // 0..127: covers 2 arrays x 64 rows
    const int cseg = (tid & 1) * 4;     // two threads per row, 4 uint4 each

    // stage tile 0 into buffer 0
    {
        const int kt = 0;
        __nv_bfloat16* dst = sA;
        const __nv_bfloat16* shi = (crow < 64) ? khg : (vhg - 64 * T_SEQ);
        const __nv_bfloat16* slo = (crow < 64) ? klg : (vlg - 64 * T_SEQ);
        int row = crow & 63;
        size_t soff = (crow < 64) ? ((size_t)(kt * 64 + row) * HDIM)
                                  : ((size_t)(crow) * T_SEQ + kt * 64);
        int doff = ((crow < 64) ? 0 : 9216) + row * KP;
#pragma unroll
        for (int e = 0; e < 4; e++) {
            *(uint4*)&dst[doff + (cseg + e) * 8] =
                *(const uint4*)&shi[soff + (cseg + e) * 8];
            *(uint4*)&dst[4608 + doff + (cseg + e) * 8] =
                *(const uint4*)&slo[soff + (cseg + e) * 8];
        }
    }
    __syncthreads();

    float m0 = -1e30f, m1 = -1e30f, l0 = 0.f, l1 = 0.f;
    float oacc[8][4] = {};
    const int qr0 = qt * 128 + w * 16 + gid;
    const int qr1 = qr0 + 8;

    for (int kt = 0; kt <= ktmax; kt++) {
        // prefetch tile kt+1 into the other buffer
        if (kt < ktmax) {
            const int nk = kt + 1;
            __nv_bfloat16* dst = sA + ((nk & 1) ? BUF_H : 0);
            const __nv_bfloat16* shi = (crow < 64) ? khg : (vhg - 64 * T_SEQ);
            const __nv_bfloat16* slo = (crow < 64) ? klg : (vlg - 64 * T_SEQ);
            int row = crow & 63;
            size_t soff = (crow < 64) ? ((size_t)(nk * 64 + row) * HDIM)
                                      : ((size_t)(crow) * T_SEQ + nk * 64);
            int doff = ((crow < 64) ? 0 : 9216) + row * KP;
#pragma unroll
            for (int e = 0; e < 4; e++) {
                *(uint4*)&dst[doff + (cseg + e) * 8] =
                    *(const uint4*)&shi[soff + (cseg + e) * 8];
                *(uint4*)&dst[4608 + doff + (cseg + e) * 8] =
                    *(const uint4*)&slo[soff + (cseg + e) * 8];
            }
        }

        if (kt * 64 <= qt * 128 + w * 16 + 15) {   // strip not fully masked
            const __nv_bfloat16* skh = sA + ((kt & 1) ? BUF_H : 0);
            const __nv_bfloat16* skl = skh + 4608;
            const __nv_bfloat16* svh = skh + 9216;
            const __nv_bfloat16* svl = skh + 13824;

            // ---- S = Q K^T ----
            float sacc[8][4] = {};
#pragma unroll
            for (int nt = 0; nt < 8; nt++)
#pragma unroll
                for (int ks = 0; ks < 4; ks++) {
                    int ad = (nt * 8 + gid) * KP + ks * 16 + 2 * tig;
                    uint32_t bh0 = *(const uint32_t*)&skh[ad];
                    uint32_t bh1 = *(const uint32_t*)&skh[ad + 8];
                    uint32_t bl0 = *(const uint32_t*)&skl[ad];
                    uint32_t bl1 = *(const uint32_t*)&skl[ad + 8];
                    mma_bf16(sacc[nt], qh[ks], bh0, bh1);
                    mma_bf16(sacc[nt], qh[ks], bl0, bl1);
                    mma_bf16(sacc[nt], ql[ks], bh0, bh1);
                }

            // ---- scale + bias + masks ----
#pragma unroll
            for (int nt = 0; nt < 8; nt++) {
                float bb0 = 0.f, bb1 = 0.f;
                if (qt < 4) {
                    bb0 = sbias[(2 * w) * 64 + kt * 8 + nt];
                    bb1 = sbias[(2 * w + 1) * 64 + kt * 8 + nt];
                }
#pragma unroll
                for (int c = 0; c < 4; c++) {
                    int kcol = kt * 64 + nt * 8 + 2 * tig + (c & 1);
                    int qr   = (c < 2) ? qr0 : qr1;
                    float s  = sacc[nt][c] * SCALE_F + ((c < 2) ? bb0 : bb1);
                    if (kcol > qr || (kcol & 15) == 15) s = -1e30f;
                    sacc[nt][c] = s;
                }
            }

            // ---- online softmax ----
            float rm0 = -1e30f, rm1 = -1e30f;
#pragma unroll
            for (int nt = 0; nt < 8; nt++) {
                rm0 = fmaxf(rm0, fmaxf(sacc[nt][0], sacc[nt][1]));
                rm1 = fmaxf(rm1, fmaxf(sacc[nt][2], sacc[nt][3]));
            }
            rm0 = fmaxf(rm0, __shfl_xor_sync(0xffffffffu, rm0, 1));
            rm0 = fmaxf(rm0, __shfl_xor_sync(0xffffffffu, rm0, 2));
            rm1 = fmaxf(rm1, __shfl_xor_sync(0xffffffffu, rm1, 1));
            rm1 = fmaxf(rm1, __shfl_xor_sync(0xffffffffu, rm1, 2));
            float mn0 = fmaxf(m0, rm0), mn1 = fmaxf(m1, rm1);
            float a0 = __expf(m0 - mn0), a1 = __expf(m1 - mn1);
            float rs0 = 0.f, rs1 = 0.f;
#pragma unroll
            for (int nt = 0; nt < 8; nt++) {
                sacc[nt][0] = __expf(sacc[nt][0] - mn0);
                sacc[nt][1] = __expf(sacc[nt][1] - mn0);
                sacc[nt][2] = __expf(sacc[nt][2] - mn1);
                sacc[nt][3] = __expf(sacc[nt][3] - mn1);
                rs0 += sacc[nt][0] + sacc[nt][1];
                rs1 += sacc[nt][2] + sacc[nt][3];
            }
            rs0 += __shfl_xor_sync(0xffffffffu, rs0, 1);
            rs0 += __shfl_xor_sync(0xffffffffu, rs0, 2);
            rs1 += __shfl_xor_sync(0xffffffffu, rs1, 1);
            rs1 += __shfl_xor_sync(0xffffffffu, rs1, 2);
            l0 = l0 * a0 + rs0; m0 = mn0;
            l1 = l1 * a1 + rs1; m1 = mn1;
#pragma unroll
            for (int dt = 0; dt < 8; dt++) {
                oacc[dt][0] *= a0; oacc[dt][1] *= a0;
                oacc[dt][2] *= a1; oacc[dt][3] *= a1;
            }

            // ---- P -> A-fragments from S accumulators (hi/lo) ----
            uint32_t ph[4][4], pl[4][4];
#pragma unroll
            for (int ks = 0; ks < 4; ks++)
#pragma unroll
                for (int half = 0; half < 2; half++) {
                    int nt = 2 * ks + half;
#pragma unroll
                    for (int rr = 0; rr < 2; rr++) {
                        float pe = sacc[nt][rr * 2 + 0];
                        float po = sacc[nt][rr * 2 + 1];
                        float he = __bfloat162float(__float2bfloat16(pe));
                        float ho = __bfloat162float(__float2bfloat16(po));
                        ph[ks][half * 2 + rr] = pack_bf2(he, ho);
                        pl[ks][half * 2 + rr] = pack_bf2(pe - he, po - ho);
                    }
                }

            // ---- O += P V ----
#pragma unroll
            for (int dt = 0; dt < 8; dt++)
#pragma unroll
                for (int ks = 0; ks < 4; ks++) {
                    int ad = (dt * 8 + gid) * KP + ks * 16 + 2 * tig;
                    uint32_t vh0 = *(const uint32_t*)&svh[ad];
                    uint32_t vh1 = *(const uint32_t*)&svh[ad + 8];
                    uint32_t vl0 = *(const uint32_t*)&svl[ad];
                    uint32_t vl1 = *(const uint32_t*)&svl[ad + 8];
                    mma_bf16(oacc[dt], ph[ks], vh0, vh1);
                    mma_bf16(oacc[dt], ph[ks], vl0, vl1);
                    mma_bf16(oacc[dt], pl[ks], vh0, vh1);
                }
        }
        __syncthreads();   // one barrier per iteration
    }

    // ---- epilogue: write y split (bf16 hi/lo) directly ----
    float inv0 = 1.0f / l0, inv1 = 1.0f / l1;
#pragma unroll
    for (int dt = 0; dt < 8; dt++) {
        int dcol = h * 64 + dt * 8 + 2 * tig;
        float y00 = oacc[dt][0] * inv0, y01 = oacc[dt][1] * inv0;
        float y10 = oacc[dt][2] * inv1, y11 = oacc[dt][3] * inv1;
        float h00 = __bfloat162float(__float2bfloat16(y00));
        float h01 = __bfloat162float(__float2bfloat16(y01));
        float h10 = __bfloat162float(__float2bfloat16(y10));
        float h11 = __bfloat162float(__float2bfloat16(y11));
        size_t i0 = ((size_t)(b_ * T_SEQ + qr0)) * CDIM + dcol;
        size_t i1 = ((size_t)(b_ * T_SEQ + qr1)) * CDIM + dcol;
        *(uint32_t*)&g_yhi[i0] = pack_bf2(h00, h01);
        *(uint32_t*)&g_ylo[i0] = pack_bf2(y00 - h00, y01 - h01);
        *(uint32_t*)&g_yhi[i1] = pack_bf2(h10, h11);
        *(uint32_t*)&g_ylo[i1] = pack_bf2(y10 - h10, y11 - h11);
    }
}

// ---------------------------------------------------------------------------

extern "C" void kernel_launch(void* const* d_in, const int* in_sizes, int n_in,
                              void* d_out, int out_size)
{
    const float* x  = (const float*)d_in[0];
    const float* ab = (const float*)d_in[1];
    const float* Wq = (const float*)d_in[2];
    const float* bq = (const float*)d_in[3];
    const float* Wk = (const float*)d_in[4];
    const float* bk = (const float*)d_in[5];
    const float* Wv = (const float*)d_in[6];
    const float* bv = (const float*)d_in[7];
    const float* Wp = (const float*)d_in[8];
    const float* bp = (const float*)d_in[9];
    float* out = (float*)d_out;

    // bf16 hi/lo conversions
    convert_x<<<(BATCH * T_SEQ * CDIM) / 1024, 256>>>(x);
    convert_w4<<<dim3((CDIM * CDIM) / 1024, 4), 256>>>(Wq, Wk, Wv, Wp);

    // QKV projections (wmma)
    hm_gemm<0><<<dim3(CDIM / 64, (BATCH * T_SEQ) / 64, 3), 128>>>(bq, bk, bv, nullptr);

    // Pre-convert K/V to MMA-ready bf16 (V transposed)
    convert_kv<<<dim3(T_SEQ / 64, BATCH * NH), 256>>>();

    // Flash attention (mma.sync, double-buffered)
    cudaFuncSetAttribute(fa_kernel, cudaFuncAttributeMaxDynamicSharedMemorySize,
                         FA_SMEM);
    fa_kernel<<<dim3(T_SEQ / 128, BATCH * NH), 256, FA_SMEM>>>(ab);

    // Output projection (reads g_yhi/g_ylo written by fa epilogue)
    hm_gemm<1><<<dim3(CDIM / 64, (BATCH * T_SEQ) / 64, 1), 128>>>(bp, nullptr, nullptr, out);
}

// round 13
// speedup vs baseline: 2.4315x; 1.1450x over previous
#include <cuda_runtime.h>
#include <cuda_bf16.h>
#include <mma.h>
#include <cstdint>

using namespace nvcuda;

#define BATCH 4
#define T_SEQ 1024
#define CDIM  512
#define NH    8
#define HDIM  64
#define SCALE_F 0.125f

// ---------------------------------------------------------------------------
// Scratch (no cudaMalloc allowed). Referenced ONLY from device code.
// ---------------------------------------------------------------------------
__device__ __align__(16) float g_q[BATCH * NH * T_SEQ * HDIM];
__device__ __align__(16) float g_k[BATCH * NH * T_SEQ * HDIM];
__device__ __align__(16) float g_v[BATCH * NH * T_SEQ * HDIM];

__device__ __align__(16) __nv_bfloat16 g_xhi[BATCH * T_SEQ * CDIM];
__device__ __align__(16) __nv_bfloat16 g_xlo[BATCH * T_SEQ * CDIM];
__device__ __align__(16) __nv_bfloat16 g_whi[4 * CDIM * CDIM];
__device__ __align__(16) __nv_bfloat16 g_wlo[4 * CDIM * CDIM];
__device__ __align__(16) __nv_bfloat16 g_yhi[BATCH * T_SEQ * CDIM];
__device__ __align__(16) __nv_bfloat16 g_ylo[BATCH * T_SEQ * CDIM];

// K/V in MMA-ready bf16 hi/lo form; V pre-transposed [bh][d][t]
__device__ __align__(16) __nv_bfloat16 g_khi[BATCH * NH * T_SEQ * HDIM];
__device__ __align__(16) __nv_bfloat16 g_klo[BATCH * NH * T_SEQ * HDIM];
__device__ __align__(16) __nv_bfloat16 g_vhi[BATCH * NH * HDIM * T_SEQ];
__device__ __align__(16) __nv_bfloat16 g_vlo[BATCH * NH * HDIM * T_SEQ];

// ---------------------------------------------------------------------------
// helpers
// ---------------------------------------------------------------------------
__device__ __forceinline__ void split4(const float* f, __nv_bfloat16* h,
                                       __nv_bfloat16* l) {
#pragma unroll
    for (int j = 0; j < 4; j++) {
        h[j] = __float2bfloat16(f[j]);
        l[j] = __float2bfloat16(f[j] - __bfloat162float(h[j]));
    }
}

__device__ __forceinline__ void mma_bf16(float* d, const uint32_t* a,
                                         uint32_t b0, uint32_t b1) {
    asm volatile(
        "mma.sync.aligned.m16n8k16.row.col.f32.bf16.bf16.f32 "
        "{%0,%1,%2,%3}, {%4,%5,%6,%7}, {%8,%9}, {%0,%1,%2,%3};"
        : "+f"(d[0]), "+f"(d[1]), "+f"(d[2]), "+f"(d[3])
        : "r"(a[0]), "r"(a[1]), "r"(a[2]), "r"(a[3]), "r"(b0), "r"(b1));
}

__device__ __forceinline__ uint32_t pack_bf2(float lo, float hi) {
    __nv_bfloat162 t = __floats2bfloat162_rn(lo, hi);  // .x = low 16 bits
    return *(uint32_t*)&t;
}

// ---------------------------------------------------------------------------
// fp32 -> bf16 hi/lo split conversions
// ---------------------------------------------------------------------------
__global__ __launch_bounds__(256)
void convert_x(const float* __restrict__ src)
{
    int i = (blockIdx.x * 256 + threadIdx.x) * 4;
    float4 v = *(const float4*)(src + i);
    float f[4] = {v.x, v.y, v.z, v.w};
    __nv_bfloat16 h[4], l[4];
    split4(f, h, l);
    *(uint2*)(g_xhi + i) = *(uint2*)h;
    *(uint2*)(g_xlo + i) = *(uint2*)l;
}

__global__ __launch_bounds__(256)
void convert_w4(const float* __restrict__ w0, const float* __restrict__ w1,
                const float* __restrict__ w2, const float* __restrict__ w3)
{
    int z = blockIdx.y;
    const float* src = (z == 0) ? w0 : (z == 1) ? w1 : (z == 2) ? w2 : w3;
    int i = (blockIdx.x * 256 + threadIdx.x) * 4;
    float4 v = *(const float4*)(src + i);
    float f[4] = {v.x, v.y, v.z, v.w};
    __nv_bfloat16 h[4], l[4];
    split4(f, h, l);
    size_t o = (size_t)z * CDIM * CDIM + i;
    *(uint2*)(g_whi + o) = *(uint2*)h;
    *(uint2*)(g_wlo + o) = *(uint2*)l;
}

// K -> khi/klo [bh][t][d];  V -> vhi/vlo transposed [bh][d][t]
__global__ __launch_bounds__(256)
void convert_kv()
{
    __shared__ float vt[64][68];

    const int bh = blockIdx.y;
    const int t0 = blockIdx.x * 64;
    const int tid = threadIdx.x;
    const size_t base = (size_t)bh * T_SEQ * HDIM;

    for (int i = tid; i < 64 * 16; i += 256) {
        int row = i >> 4, c4 = (i & 15) * 4;
        size_t idx = base + (size_t)(t0 + row) * HDIM + c4;
        float4 v = *(const float4*)&g_k[idx];
        float f[4] = {v.x, v.y, v.z, v.w};
        __nv_bfloat16 h[4], l[4];
        split4(f, h, l);
        *(uint2*)(g_khi + idx) = *(uint2*)h;
        *(uint2*)(g_klo + idx) = *(uint2*)l;
        float4 vv = *(const float4*)&g_v[idx];
        vt[row][c4 + 0] = vv.x; vt[row][c4 + 1] = vv.y;
        vt[row][c4 + 2] = vv.z; vt[row][c4 + 3] = vv.w;
    }
    __syncthreads();

    for (int i = tid; i < 64 * 16; i += 256) {
        int d = i >> 4, tq = (i & 15) * 4;
        float f[4] = {vt[tq][d], vt[tq + 1][d], vt[tq + 2][d], vt[tq + 3][d]};
        __nv_bfloat16 h[4], l[4];
        split4(f, h, l);
        size_t idx = (size_t)bh * HDIM * T_SEQ + (size_t)d * T_SEQ + t0 + tq;
        *(uint2*)(g_vhi + idx) = *(uint2*)h;
        *(uint2*)(g_vlo + idx) = *(uint2*)l;
    }
}

// ---------------------------------------------------------------------------
// Projection GEMMs via wmma, 128x128 tile, BK=32, 256 threads (8 warps 2x4,
// warp tile 64x32). bf16 2-term split. Bias staged in the SAME smem region
// (consumed into acc fragments before the mainloop's first tile store).
// ---------------------------------------------------------------------------
#define GP 40
#define MATH 5120   // halves per staged matrix (128 rows x GP)

template <int MODE>
__global__ __launch_bounds__(256, 1)
void hm_gemm(const float* __restrict__ bias0, const float* __restrict__ bias1,
             const float* __restrict__ bias2, float* __restrict__ out_proj)
{
    __shared__ __align__(32) __nv_bfloat16 sm[4 * MATH];   // 40960 B

    const int tid = threadIdx.x;
    const int wid = tid >> 5;
    const int wm = wid >> 2, wn = wid & 3;

    const int n0 = blockIdx.x * 128;
    const int m0 = blockIdx.y * 128;
    const int z  = (MODE == 0) ? (int)blockIdx.z : 3;

    const float* bias = (MODE == 0) ? ((z == 0) ? bias0 : (z == 1) ? bias1 : bias2)
                                    : bias0;
    float* outp = (MODE == 0) ? ((z == 0) ? g_q : (z == 1) ? g_k : g_v) : out_proj;

    const __nv_bfloat16* Ahi = ((MODE == 0) ? g_xhi : g_yhi) + (size_t)m0 * CDIM;
    const __nv_bfloat16* Alo = ((MODE == 0) ? g_xlo : g_ylo) + (size_t)m0 * CDIM;
    const __nv_bfloat16* Bhi = g_whi + (size_t)z * CDIM * CDIM + (size_t)n0 * CDIM;
    const __nv_bfloat16* Blo = g_wlo + (size_t)z * CDIM * CDIM + (size_t)n0 * CDIM;
    const __nv_bfloat16* srcs[4] = {Ahi, Alo, Bhi, Blo};

    // ---- bias -> smem (overlapped region; consumed before first tile store)
    float* sbias = (float*)sm;  // [16][132] floats = 8448 B
    for (int idx = tid; idx < 16 * 128; idx += 256) {
        int r = idx >> 7, c = idx & 127;
        sbias[r * 132 + c] = bias[n0 + c];
    }

    // loader: 256 threads, 2 uint4 per thread per matrix (128 rows x 32 halves)
    const int lr0 = tid >> 1;
    const int lq0 = (tid & 1) * 2;

    wmma::fragment<wmma::accumulator, 16, 16, 16, float> acc[4][2];
    uint4 pf[4][2];

#pragma unroll
    for (int mat = 0; mat < 4; mat++)
#pragma unroll
        for (int e = 0; e < 2; e++)
            pf[mat][e] = *(const uint4*)(srcs[mat] + (size_t)lr0 * CDIM + (lq0 + e) * 8);

    __syncthreads();  // sbias visible
#pragma unroll
    for (int mi = 0; mi < 4; mi++)
#pragma unroll
        for (int ni = 0; ni < 2; ni++)
            wmma::load_matrix_sync(acc[mi][ni], &sbias[wn * 32 + ni * 16], 132,
                                   wmma::mem_row_major);
    __syncthreads();  // acc init done; smem region free for tiles

    for (int kt = 0; kt < CDIM / 32; kt++) {
#pragma unroll
        for (int mat = 0; mat < 4; mat++)
#pragma unroll
            for (int e = 0; e < 2; e++)
                *(uint4*)(sm + mat * MATH + lr0 * GP + (lq0 + e) * 8) = pf[mat][e];
        __syncthreads();

        if (kt < CDIM / 32 - 1) {
            int k0 = (kt + 1) * 32;
#pragma unroll
            for (int mat = 0; mat < 4; mat++)
#pragma unroll
                for (int e = 0; e < 2; e++)
                    pf[mat][e] = *(const uint4*)(srcs[mat] + (size_t)lr0 * CDIM + k0 + (lq0 + e) * 8);
        }

#pragma unroll
        for (int ks = 0; ks < 2; ks++) {
            wmma::fragment<wmma::matrix_a, 16, 16, 16, __nv_bfloat16, wmma::row_major> fah[4], fal[4];
            wmma::fragment<wmma::matrix_b, 16, 16, 16, __nv_bfloat16, wmma::col_major> fbh[2], fbl[2];
#pragma unroll
            for (int mi = 0; mi < 4; mi++) {
                int mr = wm * 64 + mi * 16;
                wmma::load_matrix_sync(fah[mi], &sm[0 * MATH + mr * GP + ks * 16], GP);
                wmma::load_matrix_sync(fal[mi], &sm[1 * MATH + mr * GP + ks * 16], GP);
            }
#pragma unroll
            for (int ni = 0; ni < 2; ni++) {
                int nr = wn * 32 + ni * 16;
                wmma::load_matrix_sync(fbh[ni], &sm[2 * MATH + nr * GP + ks * 16], GP);
                wmma::load_matrix_sync(fbl[ni], &sm[3 * MATH + nr * GP + ks * 16], GP);
            }
#pragma unroll
            for (int mi = 0; mi < 4; mi++)
#pragma unroll
                for (int ni = 0; ni < 2; ni++) {
                    wmma::mma_sync(acc[mi][ni], fah[mi], fbh[ni], acc[mi][ni]);
                    wmma::mma_sync(acc[mi][ni], fah[mi], fbl[ni], acc[mi][ni]);
                    wmma::mma_sync(acc[mi][ni], fal[mi], fbh[ni], acc[mi][ni]);
                }
        }
        __syncthreads();
    }

    // epilogue: each 16-col tile lies within one head (offsets multiple of 16)
#pragma unroll
    for (int mi = 0; mi < 4; mi++)
#pragma unroll
        for (int ni = 0; ni < 2; ni++) {
            int m = m0 + wm * 64 + mi * 16;
            int n = n0 + wn * 32 + ni * 16;
            if (MODE == 0) {
                int b_ = m >> 10;
                int t0 = m & 1023;
                int h  = n >> 6;
                int d0 = n & 63;
                float* dst = &outp[(((size_t)(b_ * NH + h)) * T_SEQ + t0) * HDIM + d0];
                wmma::store_matrix_sync(dst, acc[mi][ni], HDIM, wmma::mem_row_major);
            } else {
                wmma::store_matrix_sync(&outp[(size_t)m * CDIM + n], acc[mi][ni],
                                        CDIM, wmma::mem_row_major);
            }
        }
}

// ---------------------------------------------------------------------------
// Flash attention on mma.sync (unchanged from passing R12 kernel)
// ---------------------------------------------------------------------------
#define KP 72
#define BUF_H 18432
#define FA_SMEM (2 * BUF_H * 2 + 4096)

__global__ __launch_bounds__(256, 1)
void fa_kernel(const float* __restrict__ attn_bias)
{
    extern __shared__ char fsh[];
    __nv_bfloat16* sA    = (__nv_bfloat16*)fsh;
    float*         sbias = (float*)(fsh + 2 * BUF_H * 2);

    const int bh = blockIdx.y;
    const int h  = bh & (NH - 1);
    const int b_ = bh >> 3;
    const int qt = (int)(gridDim.x - 1) - (int)blockIdx.x;
    const int tid = threadIdx.x;
    const int w   = tid >> 5, lane = tid & 31;
    const int gid = lane >> 2, tig = lane & 3;

    const float* qg = g_q + (size_t)bh * T_SEQ * HDIM + (size_t)qt * 128 * HDIM;
    const __nv_bfloat16* khg = g_khi + (size_t)bh * T_SEQ * HDIM;
    const __nv_bfloat16* klg = g_klo + (size_t)bh * T_SEQ * HDIM;
    const __nv_bfloat16* vhg = g_vhi + (size_t)bh * HDIM * T_SEQ;
    const __nv_bfloat16* vlg = g_vlo + (size_t)bh * HDIM * T_SEQ;

    for (int i = tid; i < 128 * 16; i += 256) {
        int row = i >> 4, c4 = (i & 15) * 4;
        float4 v = *(const float4*)&qg[(size_t)row * HDIM + c4];
        float f[4] = {v.x, v.y, v.z, v.w};
        __nv_bfloat16 hh[4], ll[4];
        split4(f, hh, ll);
#pragma unroll
        for (int j = 0; j < 4; j++) {
            sA[row * KP + c4 + j]        = hh[j];
            sA[9216 + row * KP + c4 + j] = ll[j];
        }
    }
    if (qt < 4) {
        const float* bsrc = attn_bias + h * 64 * 64 + (qt * 16) * 64;
        for (int i = tid; i < 16 * 64; i += 256) sbias[i] = bsrc[i];
    }
    __syncthreads();

    uint32_t qh[4][4], ql[4][4];
    const int qrl = w * 16 + gid;
#pragma unroll
    for (int ks = 0; ks < 4; ks++) {
        int ad = qrl * KP + ks * 16 + 2 * tig;
        qh[ks][0] = *(const uint32_t*)&sA[ad];
        qh[ks][1] = *(const uint32_t*)&sA[ad + 8 * KP];
        qh[ks][2] = *(const uint32_t*)&sA[ad + 8];
        qh[ks][3] = *(const uint32_t*)&sA[ad + 8 * KP + 8];
        ql[ks][0] = *(const uint32_t*)&sA[9216 + ad];
        ql[ks][1] = *(const uint32_t*)&sA[9216 + ad + 8 * KP];
        ql[ks][2] = *(const uint32_t*)&sA[9216 + ad + 8];
        ql[ks][3] = *(const uint32_t*)&sA[9216 + ad + 8 * KP + 8];
    }
    __syncthreads();

    const int ktmax = 2 * qt + 1;
    const int crow = tid >> 1;
    const int cseg = (tid & 1) * 4;

    {
        const int kt = 0;
        __nv_bfloat16* dst = sA;
        const __nv_bfloat16* shi = (crow < 64) ? khg : (vhg - 64 * T_SEQ);
        const __nv_bfloat16* slo = (crow < 64) ? klg : (vlg - 64 * T_SEQ);
        int row = crow & 63;
        size_t soff = (crow < 64) ? ((size_t)(kt * 64 + row) * HDIM)
                                  : ((size_t)(crow) * T_SEQ + kt * 64);
        int doff = ((crow < 64) ? 0 : 9216) + row * KP;
#pragma unroll
        for (int e = 0; e < 4; e++) {
            *(uint4*)&dst[doff + (cseg + e) * 8] =
                *(const uint4*)&shi[soff + (cseg + e) * 8];
            *(uint4*)&dst[4608 + doff + (cseg + e) * 8] =
                *(const uint4*)&slo[soff + (cseg + e) * 8];
        }
    }
    __syncthreads();

    float m0 = -1e30f, m1 = -1e30f, l0 = 0.f, l1 = 0.f;
    float oacc[8][4] = {};
    const int qr0 = qt * 128 + w * 16 + gid;
    const int qr1 = qr0 + 8;

    for (int kt = 0; kt <= ktmax; kt++) {
        if (kt < ktmax) {
            const int nk = kt + 1;
            __nv_bfloat16* dst = sA + ((nk & 1) ? BUF_H : 0);
            const __nv_bfloat16* shi = (crow < 64) ? khg : (vhg - 64 * T_SEQ);
            const __nv_bfloat16* slo = (crow < 64) ? klg : (vlg - 64 * T_SEQ);
            int row = crow & 63;
            size_t soff = (crow < 64) ? ((size_t)(nk * 64 + row) * HDIM)
                                      : ((size_t)(crow) * T_SEQ + nk * 64);
            int doff = ((crow < 64) ? 0 : 9216) + row * KP;
#pragma unroll
            for (int e = 0; e < 4; e++) {
                *(uint4*)&dst[doff + (cseg + e) * 8] =
                    *(const uint4*)&shi[soff + (cseg + e) * 8];
                *(uint4*)&dst[4608 + doff + (cseg + e) * 8] =
                    *(const uint4*)&slo[soff + (cseg + e) * 8];
            }
        }

        if (kt * 64 <= qt * 128 + w * 16 + 15) {
            const __nv_bfloat16* skh = sA + ((kt & 1) ? BUF_H : 0);
            const __nv_bfloat16* skl = skh + 4608;
            const __nv_bfloat16* svh = skh + 9216;
            const __nv_bfloat16* svl = skh + 13824;

            float sacc[8][4] = {};
#pragma unroll
            for (int nt = 0; nt < 8; nt++)
#pragma unroll
                for (int ks = 0; ks < 4; ks++) {
                    int ad = (nt * 8 + gid) * KP + ks * 16 + 2 * tig;
                    uint32_t bh0 = *(const uint32_t*)&skh[ad];
                    uint32_t bh1 = *(const uint32_t*)&skh[ad + 8];
                    uint32_t bl0 = *(const uint32_t*)&skl[ad];
                    uint32_t bl1 = *(const uint32_t*)&skl[ad + 8];
                    mma_bf16(sacc[nt], qh[ks], bh0, bh1);
                    mma_bf16(sacc[nt], qh[ks], bl0, bl1);
                    mma_bf16(sacc[nt], ql[ks], bh0, bh1);
                }

#pragma unroll
            for (int nt = 0; nt < 8; nt++) {
                float bb0 = 0.f, bb1 = 0.f;
                if (qt < 4) {
                    bb0 = sbias[(2 * w) * 64 + kt * 8 + nt];
                    bb1 = sbias[(2 * w + 1) * 64 + kt * 8 + nt];
                }
#pragma unroll
                for (int c = 0; c < 4; c++) {
                    int kcol = kt * 64 + nt * 8 + 2 * tig + (c & 1);
                    int qr   = (c < 2) ? qr0 : qr1;
                    float s  = sacc[nt][c] * SCALE_F + ((c < 2) ? bb0 : bb1);
                    if (kcol > qr || (kcol & 15) == 15) s = -1e30f;
                    sacc[nt][c] = s;
                }
            }

            float rm0 = -1e30f, rm1 = -1e30f;
#pragma unroll
            for (int nt = 0; nt < 8; nt++) {
                rm0 = fmaxf(rm0, fmaxf(sacc[nt][0], sacc[nt][1]));
                rm1 = fmaxf(rm1, fmaxf(sacc[nt][2], sacc[nt][3]));
            }
            rm0 = fmaxf(rm0, __shfl_xor_sync(0xffffffffu, rm0, 1));
            rm0 = fmaxf(rm0, __shfl_xor_sync(0xffffffffu, rm0, 2));
            rm1 = fmaxf(rm1, __shfl_xor_sync(0xffffffffu, rm1, 1));
            rm1 = fmaxf(rm1, __shfl_xor_sync(0xffffffffu, rm1, 2));
            float mn0 = fmaxf(m0, rm0), mn1 = fmaxf(m1, rm1);
            float a0 = __expf(m0 - mn0), a1 = __expf(m1 - mn1);
            float rs0 = 0.f, rs1 = 0.f;
#pragma unroll
            for (int nt = 0; nt < 8; nt++) {
                sacc[nt][0] = __expf(sacc[nt][0] - mn0);
                sacc[nt][1] = __expf(sacc[nt][1] - mn0);
                sacc[nt][2] = __expf(sacc[nt][2] - mn1);
                sacc[nt][3] = __expf(sacc[nt][3] - mn1);
                rs0 += sacc[nt][0] + sacc[nt][1];
                rs1 += sacc[nt][2] + sacc[nt][3];
            }
            rs0 += __shfl_xor_sync(0xffffffffu, rs0, 1);
            rs0 += __shfl_xor_sync(0xffffffffu, rs0, 2);
            rs1 += __shfl_xor_sync(0xffffffffu, rs1, 1);
            rs1 += __shfl_xor_sync(0xffffffffu, rs1, 2);
            l0 = l0 * a0 + rs0; m0 = mn0;
            l1 = l1 * a1 + rs1; m1 = mn1;
#pragma unroll
            for (int dt = 0; dt < 8; dt++) {
                oacc[dt][0] *= a0; oacc[dt][1] *= a0;
                oacc[dt][2] *= a1; oacc[dt][3] *= a1;
            }

            uint32_t ph[4][4], pl[4][4];
#pragma unroll
            for (int ks = 0; ks < 4; ks++)
#pragma unroll
                for (int half = 0; half < 2; half++) {
                    int nt = 2 * ks + half;
#pragma unroll
                    for (int rr = 0; rr < 2; rr++) {
                        float pe = sacc[nt][rr * 2 + 0];
                        float po = sacc[nt][rr * 2 + 1];
                        float he = __bfloat162float(__float2bfloat16(pe));
                        float ho = __bfloat162float(__float2bfloat16(po));
                        ph[ks][half * 2 + rr] = pack_bf2(he, ho);
                        pl[ks][half * 2 + rr] = pack_bf2(pe - he, po - ho);
                    }
                }

#pragma unroll
            for (int dt = 0; dt < 8; dt++)
#pragma unroll
                for (int ks = 0; ks < 4; ks++) {
                    int ad = (dt * 8 + gid) * KP + ks * 16 + 2 * tig;
                    uint32_t vh0 = *(const uint32_t*)&svh[ad];
                    uint32_t vh1 = *(const uint32_t*)&svh[ad + 8];
                    uint32_t vl0 = *(const uint32_t*)&svl[ad];
                    uint32_t vl1 = *(const uint32_t*)&svl[ad + 8];
                    mma_bf16(oacc[dt], ph[ks], vh0, vh1);
                    mma_bf16(oacc[dt], ph[ks], vl0, vl1);
                    mma_bf16(oacc[dt], pl[ks], vh0, vh1);
                }
        }
        __syncthreads();
    }

    float inv0 = 1.0f / l0, inv1 = 1.0f / l1;
#pragma unroll
    for (int dt = 0; dt < 8; dt++) {
        int dcol = h * 64 + dt * 8 + 2 * tig;
        float y00 = oacc[dt][0] * inv0, y01 = oacc[dt][1] * inv0;
        float y10 = oacc[dt][2] * inv1, y11 = oacc[dt][3] * inv1;
        float h00 = __bfloat162float(__float2bfloat16(y00));
        float h01 = __bfloat162float(__float2bfloat16(y01));
        float h10 = __bfloat162float(__float2bfloat16(y10));
        float h11 = __bfloat162float(__float2bfloat16(y11));
        size_t i0 = ((size_t)(b_ * T_SEQ + qr0)) * CDIM + dcol;
        size_t i1 = ((size_t)(b_ * T_SEQ + qr1)) * CDIM + dcol;
        *(uint32_t*)&g_yhi[i0] = pack_bf2(h00, h01);
        *(uint32_t*)&g_ylo[i0] = pack_bf2(y00 - h00, y01 - h01);
        *(uint32_t*)&g_yhi[i1] = pack_bf2(h10, h11);
        *(uint32_t*)&g_ylo[i1] = pack_bf2(y10 - h10, y11 - h11);
    }
}

// ---------------------------------------------------------------------------

extern "C" void kernel_launch(void* const* d_in, const int* in_sizes, int n_in,
                              void* d_out, int out_size)
{
    const float* x  = (const float*)d_in[0];
    const float* ab = (const float*)d_in[1];
    const float* Wq = (const float*)d_in[2];
    const float* bq = (const float*)d_in[3];
    const float* Wk = (const float*)d_in[4];
    const float* bk = (const float*)d_in[5];
    const float* Wv = (const float*)d_in[6];
    const float* bv = (const float*)d_in[7];
    const float* Wp = (const float*)d_in[8];
    const float* bp = (const float*)d_in[9];
    float* out = (float*)d_out;

    // bf16 hi/lo conversions
    convert_x<<<(BATCH * T_SEQ * CDIM) / 1024, 256>>>(x);
    convert_w4<<<dim3((CDIM * CDIM) / 1024, 4), 256>>>(Wq, Wk, Wv, Wp);

    // QKV projections (wmma, 128x128 tiles)
    hm_gemm<0><<<dim3(CDIM / 128, (BATCH * T_SEQ) / 128, 3), 256>>>(bq, bk, bv, nullptr);

    // Pre-convert K/V to MMA-ready bf16 (V transposed)
    convert_kv<<<dim3(T_SEQ / 64, BATCH * NH), 256>>>();

    // Flash attention (mma.sync, double-buffered)
    cudaFuncSetAttribute(fa_kernel, cudaFuncAttributeMaxDynamicSharedMemorySize,
                         FA_SMEM);
    fa_kernel<<<dim3(T_SEQ / 128, BATCH * NH), 256, FA_SMEM>>>(ab);

    // Output projection
    hm_gemm<1><<<dim3(CDIM / 128, (BATCH * T_SEQ) / 128, 1), 256>>>(bp, nullptr, nullptr, out);
}